// round 17
// baseline (speedup 1.0000x reference)
#include <cuda_runtime.h>
#include <cuda_fp16.h>
#include <math_constants.h>

#define SEQ  4096
#define HID  768
#define NB   8
#define KH   385   // HID/2 + 1 (Hermitian half + Nyquist)
#define KHP  416   // padded k-stride: 416 half2 = 1664 B = 13*128 (sector-aligned)
#define AROWS 8    // real rows per block -> 4 complex FFTs (pair trick)
#define KT   32    // k-tile width for B1/B2
#define NKT  13    // ceil(385/32)

// ---------------------------------------------------------------- device state
__device__ __half2 g_Yh [NB * SEQ * KHP];       // A out:  [b][s][k]   (~55 MB, fp16)
__device__ __half2 g_Y2h[NB * 64 * 64 * KHP];   // B1 out: [b][m0][s0][k] (~55 MB)

// ---------------------------------------------------------------- helpers
__device__ __forceinline__ float2 cadd(float2 a, float2 b){ return make_float2(a.x+b.x, a.y+b.y); }
__device__ __forceinline__ float2 csub(float2 a, float2 b){ return make_float2(a.x-b.x, a.y-b.y); }
__device__ __forceinline__ float2 mni (float2 a){ return make_float2(a.y, -a.x); }   // * (-i)
__device__ __forceinline__ float2 cmul(float2 a, float2 w){
    return make_float2(fmaf(a.x, w.x, -a.y * w.y), fmaf(a.x, w.y, a.y * w.x));
}
__device__ __forceinline__ int rev8x8(int m){ return ((m & 7) << 3) | (m >> 3); }
__device__ __forceinline__ __half2 f2h(float2 v){ return __floats2half2_rn(v.x, v.y); }
__device__ __forceinline__ float2 h2f(__half2 h){ return __half22float2(h); }
// e^{-i*pi*x}
__device__ __forceinline__ float2 wexp(float x){
    float s, c; sincospif(-x, &s, &c); return make_float2(c, s);
}

// 8-point DFT (negative exponent), in place. ~56 flops.
__device__ __forceinline__ void dft8(float2* v) {
    const float C = 0.70710678118654752f;
    float2 t0 = cadd(v[0], v[4]), t1 = csub(v[0], v[4]);
    float2 t2 = cadd(v[2], v[6]), t3 = csub(v[2], v[6]);
    float2 E0 = cadd(t0, t2), E2 = csub(t0, t2);
    float2 mt3 = mni(t3);
    float2 E1 = cadd(t1, mt3), E3 = csub(t1, mt3);
    float2 u0 = cadd(v[1], v[5]), u1 = csub(v[1], v[5]);
    float2 u2 = cadd(v[3], v[7]), u3 = csub(v[3], v[7]);
    float2 O0 = cadd(u0, u2), O2 = csub(u0, u2);
    float2 mu3 = mni(u3);
    float2 O1 = cadd(u1, mu3), O3 = csub(u1, mu3);
    float2 W1 = make_float2(C * (O1.x + O1.y), C * (O1.y - O1.x));   // W8^1 * O1
    float2 W2 = mni(O2);                                             // W8^2 * O2
    float2 W3 = make_float2(C * (O3.y - O3.x), -C * (O3.x + O3.y));  // W8^3 * O3
    v[0] = cadd(E0, O0);  v[4] = csub(E0, O0);
    v[1] = cadd(E1, W1);  v[5] = csub(E1, W1);
    v[2] = cadd(E2, W2);  v[6] = csub(E2, W2);
    v[3] = cadd(E3, W3);  v[7] = csub(E3, W3);
}

// Apply W64^{i*k} to v[1..7] via power recurrence from w1 = W64^{i}.
__device__ __forceinline__ void tw64(float2* v, int i) {
    float2 w1 = wexp((float)i / 32.0f);
    float2 w = w1;
    v[1] = cmul(v[1], w);
    #pragma unroll
    for (int k = 2; k < 8; k++) { w = cmul(w, w1); v[k] = cmul(v[k], w); }
}

// ------------------------------------------------- stage A: hidden-dim FFT(768)
// 8 real rows -> 4 packed complex rows (pair trick). Phase 1 loads x straight
// from global into registers; epilogue mirror indices computed algebraically.
__global__ __launch_bounds__(256) void k_stageA(const float* __restrict__ x) {
    __shared__ float2 sG[4 * 12 * 65];          // 24.96 KB

    int rowBase = blockIdx.x * AROWS;
    int b    = rowBase >> 12;
    int srow = rowBase & 4095;
    int t = threadIdx.x;

    // ---- phase 1: per-thread FFT-12, inputs direct from global ----
    {
        int f = t >> 6, h0 = t & 63;
        const float* xr0 = x + ((size_t)rowBase + 2 * f) * HID + h0;
        const float* xr1 = xr0 + HID;
        float2 z[12];
        #pragma unroll
        for (int h1 = 0; h1 < 12; h1++)
            z[h1] = make_float2(__ldg(xr0 + 64 * h1), __ldg(xr1 + 64 * h1));

        float2 A[3][4];
        #pragma unroll
        for (int n2 = 0; n2 < 3; n2++) {
            float2 a0 = cadd(z[n2],     z[6 + n2]);
            float2 a1 = csub(z[n2],     z[6 + n2]);
            float2 a2 = cadd(z[3 + n2], z[9 + n2]);
            float2 a3 = csub(z[3 + n2], z[9 + n2]);
            A[n2][0] = cadd(a0, a2);
            A[n2][1] = cadd(a1, mni(a3));
            A[n2][2] = csub(a0, a2);
            A[n2][3] = csub(a1, mni(a3));
        }
        const float H = 0.5f, S3 = 0.86602540378443865f;
        A[1][1] = cmul(A[1][1], make_float2( S3, -H ));   // W12^1
        A[1][2] = cmul(A[1][2], make_float2( H , -S3));   // W12^2
        A[1][3] = mni (A[1][3]);                          // W12^3
        A[2][1] = cmul(A[2][1], make_float2( H , -S3));   // W12^2
        A[2][2] = cmul(A[2][2], make_float2(-H , -S3));   // W12^4
        A[2][3] = make_float2(-A[2][3].x, -A[2][3].y);    // W12^6
        float2 Xo[12];
        #pragma unroll
        for (int k1p = 0; k1p < 4; k1p++) {
            float2 b0 = A[0][k1p], b1 = A[1][k1p], b2 = A[2][k1p];
            float2 tt = cadd(b1, b2), dd = csub(b1, b2);
            float2 s  = make_float2(fmaf(-0.5f, tt.x, b0.x),
                                    fmaf(-0.5f, tt.y, b0.y));
            float2 md = mni(dd);
            float2 e  = make_float2(S3 * md.x, S3 * md.y);
            Xo[k1p]     = cadd(b0, tt);
            Xo[k1p + 4] = cadd(s, e);
            Xo[k1p + 8] = csub(s, e);
        }
        // W768^{h0*q} twiddle via recurrence from w1 = W768^{h0}
        sG[(f * 12 + 0) * 65 + h0] = Xo[0];
        float2 w1 = wexp((float)h0 / 384.0f);
        float2 w = w1;
        sG[(f * 12 + 1) * 65 + h0] = cmul(Xo[1], w);
        #pragma unroll
        for (int q = 2; q < 12; q++) {
            w = cmul(w, w1);
            sG[(f * 12 + q) * 65 + h0] = cmul(Xo[q], w);
        }
    }
    __syncthreads();

    // ---- phase 2: 48 independent 64-pt FFTs (radix-8 DIF, 2 stages) ----
    for (int task = t; task < 48 * 8; task += 256) {
        int ff = task % 48, i = task / 48;
        float2* s = &sG[ff * 65];
        float2 v[8];
        #pragma unroll
        for (int j = 0; j < 8; j++) v[j] = s[i + 8 * j];
        dft8(v);
        tw64(v, i);
        #pragma unroll
        for (int j = 0; j < 8; j++) s[i + 8 * j] = v[j];
    }
    __syncthreads();
    for (int task = t; task < 48 * 8; task += 256) {
        int ff = task % 48, blk = task / 48;
        float2* s = &sG[ff * 65 + 8 * blk];
        float2 v[8];
        #pragma unroll
        for (int j = 0; j < 8; j++) v[j] = s[j];
        dft8(v);
        #pragma unroll
        for (int j = 0; j < 8; j++) s[j] = v[j];
    }
    __syncthreads();

    // ---- unpack pairs + write g_Yh[b][s][k] (fp16, padded stride KHP)
    for (int k = t; k < KH; k += 256) {
        int k2 = k / 12, k1 = k - k2 * 12;
        int p  = rev8x8(k2);
        // mirror bin km = (768-k)%768: since 768%12==0, algebraic split
        int kk1 = (k1 > 0) ? (12 - k1) : 0;
        int kk2 = (k1 > 0) ? (63 - k2) : ((64 - k2) & 63);
        int pk = rev8x8(kk2);
        #pragma unroll
        for (int f = 0; f < 4; f++) {
            float2 Z  = sG[(f * 12 + k1)  * 65 + p];
            float2 Zk = sG[(f * 12 + kk1) * 65 + pk];
            float2 Ya = make_float2(0.5f * (Z.x + Zk.x), 0.5f * (Z.y - Zk.y));
            float2 Yb = make_float2(0.5f * (Z.y + Zk.y), 0.5f * (Zk.x - Z.x));
            g_Yh[((size_t)(b * SEQ) + srow + 2 * f)     * KHP + k] = f2h(Ya);
            g_Yh[((size_t)(b * SEQ) + srow + 2 * f + 1) * KHP + k] = f2h(Yb);
        }
    }
}

// --------------------------------------- B1: seq FFT step 1 (over s1) + twiddle
__global__ __launch_bounds__(256) void k_B1() {
    __shared__ float2 tile[64 * KT];   // 16 KB
    int k0 = blockIdx.x * KT;
    int s0 = blockIdx.y;
    int b  = blockIdx.z;
    int t  = threadIdx.x;
    int kk = t & 31, r0 = t >> 5;
    int k  = k0 + kk;
    bool ok = (k < KH);

    float2 v[8];
    #pragma unroll
    for (int j = 0; j < 8; j++)
        v[j] = ok ? h2f(g_Yh[((size_t)(b * SEQ) + s0 + 64 * (r0 + 8 * j)) * KHP + k])
                  : make_float2(0.f, 0.f);
    dft8(v);
    tw64(v, r0);                       // W64^{r0*k}
    #pragma unroll
    for (int j = 0; j < 8; j++) tile[(r0 + 8 * j) * KT + kk] = v[j];
    __syncthreads();

    float2 u[8];
    #pragma unroll
    for (int j = 0; j < 8; j++) u[j] = tile[(8 * r0 + j) * KT + kk];
    dft8(u);

    float2 w    = wexp((float)(s0 * r0) / 2048.0f);
    float2 step = wexp((float)(8 * s0) / 2048.0f);
    #pragma unroll
    for (int j = 0; j < 8; j++) {
        int m0 = 8 * j + r0;
        if (ok)
            g_Y2h[(((size_t)b * 64 + m0) * 64 + s0) * KHP + k] = f2h(cmul(u[j], w));
        w = cmul(w, step);
    }
}

// --------------------------------------- B2: seq FFT step 2, real part + mirror
__global__ __launch_bounds__(256) void k_B2(float* __restrict__ out) {
    __shared__ float2 tile[64 * KT];   // 16 KB
    int k0 = blockIdx.x * KT;
    int m0 = blockIdx.y;
    int b  = blockIdx.z;
    int t  = threadIdx.x;
    int kk = t & 31, r0 = t >> 5;
    int k  = k0 + kk;
    bool ok = (k < KH);

    float2 v[8];
    #pragma unroll
    for (int j = 0; j < 8; j++)
        v[j] = ok ? h2f(g_Y2h[(((size_t)b * 64 + m0) * 64 + (r0 + 8 * j)) * KHP + k])
                  : make_float2(0.f, 0.f);
    dft8(v);
    tw64(v, r0);
    #pragma unroll
    for (int j = 0; j < 8; j++) tile[(r0 + 8 * j) * KT + kk] = v[j];
    __syncthreads();

    float2 u[8];
    #pragma unroll
    for (int j = 0; j < 8; j++) u[j] = tile[(8 * r0 + j) * KT + kk];
    dft8(u);

    bool domir = (k >= 1 && k <= 383);
    #pragma unroll
    for (int j = 0; j < 8; j++) {
        int m1 = 8 * j + r0;
        float zr = u[j].x;
        int m = m0 + 64 * m1;
        if (ok)
            out[((size_t)b * SEQ + m) * HID + k] = zr;
        if (domir) {
            int mp = (SEQ - m) & 4095;
            out[((size_t)b * SEQ + mp) * HID + (HID - k)] = zr;
        }
    }
}

extern "C" void kernel_launch(void* const* d_in, const int* in_sizes, int n_in,
                              void* d_out, int out_size) {
    (void)in_sizes; (void)n_in; (void)out_size;
    const float* x = (const float*)d_in[0];
    float* out = (float*)d_out;

    k_stageA <<<NB * SEQ / AROWS, 256>>>(x);        // 4096 blocks
    k_B1     <<<dim3(NKT, 64, NB), 256>>>();        // 6656 blocks
    k_B2     <<<dim3(NKT, 64, NB), 256>>>(out);     // 6656 blocks
}